// round 4
// baseline (speedup 1.0000x reference)
#include <cuda_runtime.h>
#include <math.h>
#include <stddef.h>

#define BB 4
#define NN 1024
#define DD 1024
#define EE 32
#define HH 4096
#define LN_EPS 1e-5f
#define PS_EPS 1e-9f

// ---------------- scratch (device globals) ----------------
__device__ __align__(16) float g_q[EE * DD];
__device__ __align__(16) float g_logits[BB * NN * EE];    // [b][n][e]
__device__ __align__(16) float g_logitsT[BB * EE * NN];   // [b][e][n]
__device__ __align__(16) float g_cwT[BB * EE * NN];       // combine weights [b][e][n]
__device__ __align__(16) float2 g_minv[BB * EE];          // (max, 1/sum) per (b,e)
__device__ float g_cwterm[BB * NN];
__device__ float g_cwdiag[BB * EE];
__device__ float g_dwterm[BB * EE];
__device__ __align__(16) float g_slots_part[8][BB * EE * DD];
__device__ __align__(16) float g_h1p[4][EE * BB * HH];    // pre-gelu partials (k-split 4)
__device__ __align__(16) float g_eo_part[16][BB * EE * DD];
__device__ __align__(16) float g_eo[BB * EE * DD];

// ---------------- K1: q = LayerNorm(phi*qg+qb)*scale ----------------
__global__ __launch_bounds__(256) void k_qnorm(
    const float* __restrict__ phi, const float* __restrict__ qg,
    const float* __restrict__ qb, const float* __restrict__ lng,
    const float* __restrict__ lnb, const float* __restrict__ scale_p) {
    int e = blockIdx.x;
    int t = threadIdx.x;
    __shared__ float v[DD];
    __shared__ float red[256];

    float local = 0.f;
    for (int d = t; d < DD; d += 256) {
        float x = phi[e * DD + d] * qg[d] + qb[d];
        v[d] = x;
        local += x;
    }
    red[t] = local; __syncthreads();
    for (int s = 128; s > 0; s >>= 1) { if (t < s) red[t] += red[t + s]; __syncthreads(); }
    float mean = red[0] * (1.f / DD);
    __syncthreads();

    float lv = 0.f;
    for (int d = t; d < DD; d += 256) { float c = v[d] - mean; lv += c * c; }
    red[t] = lv; __syncthreads();
    for (int s = 128; s > 0; s >>= 1) { if (t < s) red[t] += red[t + s]; __syncthreads(); }
    float var = red[0] * (1.f / DD);
    float rstd = rsqrtf(var + LN_EPS);
    float sc = *scale_p;
    for (int d = t; d < DD; d += 256)
        g_q[e * DD + d] = ((v[d] - mean) * rstd * lng[d] + lnb[d]) * sc;
}

// ---------------- K2: logits (writes both layouts) ----------------
__global__ __launch_bounds__(256) void k_logits(
    const float* __restrict__ x, const float* __restrict__ kg,
    const float* __restrict__ kb) {
    int b = blockIdx.y;
    int n0 = blockIdx.x * 32;
    int t = threadIdx.x;
    int e = t & 31;
    int rq = t >> 5;  // 0..7

    __shared__ float xs[32][33];
    __shared__ float qs[32][33];

    float acc0 = 0.f, acc1 = 0.f, acc2 = 0.f, acc3 = 0.f;
    int c = t & 31;
    for (int dc = 0; dc < DD; dc += 32) {
        for (int r = t >> 5; r < 32; r += 8) {
            int d = dc + c;
            xs[r][c] = x[((size_t)(b * NN) + (n0 + r)) * DD + d] * kg[d] + kb[d];
        }
        for (int r = t >> 5; r < 32; r += 8)
            qs[r][c] = g_q[r * DD + dc + c];
        __syncthreads();
#pragma unroll
        for (int k = 0; k < 32; k++) {
            float qv = qs[e][k];
            acc0 += xs[rq * 4 + 0][k] * qv;
            acc1 += xs[rq * 4 + 1][k] * qv;
            acc2 += xs[rq * 4 + 2][k] * qv;
            acc3 += xs[rq * 4 + 3][k] * qv;
        }
        __syncthreads();
    }
#pragma unroll
    for (int r = 0; r < 4; r++) {
        float a = (r == 0) ? acc0 : (r == 1) ? acc1 : (r == 2) ? acc2 : acc3;
        int n = n0 + rq * 4 + r;
        g_logits[((b * NN) + n) * EE + e] = a;
        g_logitsT[((size_t)(b * EE) + e) * NN + n] = a;
    }
}

// ---------------- K3: dispatch softmax stats per (b,e) + dw metric ----------------
__global__ __launch_bounds__(256) void k_dstats() {
    int be = blockIdx.x;
    int t = threadIdx.x;
    __shared__ float red[256];

    const float4* L = reinterpret_cast<const float4*>(g_logitsT + (size_t)be * NN);
    float4 v = L[t];

    float m = fmaxf(fmaxf(v.x, v.y), fmaxf(v.z, v.w));
    red[t] = m; __syncthreads();
    for (int s = 128; s > 0; s >>= 1) { if (t < s) red[t] = fmaxf(red[t], red[t + s]); __syncthreads(); }
    m = red[0]; __syncthreads();

    float ex0 = expf(v.x - m), ex1 = expf(v.y - m), ex2 = expf(v.z - m), ex3 = expf(v.w - m);
    red[t] = ex0 + ex1 + ex2 + ex3; __syncthreads();
    for (int s = 128; s > 0; s >>= 1) { if (t < s) red[t] += red[t + s]; __syncthreads(); }
    float ssum = red[0]; __syncthreads();

    red[t] = ex0 * ex0 + ex1 * ex1 + ex2 * ex2 + ex3 * ex3; __syncthreads();
    for (int s = 128; s > 0; s >>= 1) { if (t < s) red[t] += red[t + s]; __syncthreads(); }

    if (t == 0) {
        float ssq = red[0];
        float inv = 1.f / ssum;
        g_minv[be] = make_float2(m, inv);
        float wsq = ssq * inv * inv;
        float rs = rsqrtf(wsq + PS_EPS);
        float rn = (ssum * inv) * rs;
        g_dwterm[be] = rn * rn;
    }
}

// ---------------- K4: slots partials (register micro-tile GEMM) ----------------
// grid (dt=8, ns=8, b=4) = 256 blocks; thread: 4e x 4d (float4), 16 accs
__global__ __launch_bounds__(256) void k_slots(const float* __restrict__ x) {
    int dt = blockIdx.x;
    int ns = blockIdx.y;
    int b = blockIdx.z;
    int t = threadIdx.x;
    int td = t & 31;   // d-quad
    int te = t >> 5;   // 0..7 -> experts te*4..te*4+3
    int d0 = dt * 128;
    int n0 = ns * 128;

    __shared__ float4 xs4[32][32];   // [nn][d-quad], 16 KB
    __shared__ float dwsT[32][33];   // [e][nn]

    float4 a0 = make_float4(0.f, 0.f, 0.f, 0.f), a1 = a0, a2 = a0, a3 = a0;

    for (int c = 0; c < 4; c++) {
        int nc = n0 + c * 32;
        __syncthreads();
        for (int i = t; i < 1024; i += 256) {
            int row = i >> 5, q = i & 31;
            xs4[row][q] = *reinterpret_cast<const float4*>(
                x + ((size_t)(b * NN) + nc + row) * DD + d0 + q * 4);
        }
        for (int i = t; i < 1024; i += 256) {
            int e = i >> 5, nn = i & 31;
            float2 mi = g_minv[b * EE + e];
            float lv = g_logitsT[((size_t)(b * EE) + e) * NN + nc + nn];
            dwsT[e][nn] = expf(lv - mi.x) * mi.y;
        }
        __syncthreads();
#pragma unroll
        for (int k = 0; k < 32; k++) {
            float4 xv = xs4[k][td];
            float w0 = dwsT[te * 4 + 0][k];
            float w1 = dwsT[te * 4 + 1][k];
            float w2 = dwsT[te * 4 + 2][k];
            float w3 = dwsT[te * 4 + 3][k];
            a0.x += w0 * xv.x; a0.y += w0 * xv.y; a0.z += w0 * xv.z; a0.w += w0 * xv.w;
            a1.x += w1 * xv.x; a1.y += w1 * xv.y; a1.z += w1 * xv.z; a1.w += w1 * xv.w;
            a2.x += w2 * xv.x; a2.y += w2 * xv.y; a2.z += w2 * xv.z; a2.w += w2 * xv.w;
            a3.x += w3 * xv.x; a3.y += w3 * xv.y; a3.z += w3 * xv.z; a3.w += w3 * xv.w;
        }
    }
    size_t base = ((size_t)(b * EE) + te * 4) * DD + d0 + td * 4;
    *reinterpret_cast<float4*>(&g_slots_part[ns][base + 0 * DD]) = a0;
    *reinterpret_cast<float4*>(&g_slots_part[ns][base + 1 * DD]) = a1;
    *reinterpret_cast<float4*>(&g_slots_part[ns][base + 2 * DD]) = a2;
    *reinterpret_cast<float4*>(&g_slots_part[ns][base + 3 * DD]) = a3;
}

// ---------------- K5: w1 pass (k-split 4, slot reduction fused) ----------------
__global__ __launch_bounds__(128) void k_w1(const float* __restrict__ w1) {
    int e = blockIdx.z;
    int ks = blockIdx.y;
    int j0 = blockIdx.x * 512 + threadIdx.x * 4;
    int d0 = ks * 256;

    __shared__ float ssp[256 * 4];  // [d][b]
    for (int i = threadIdx.x; i < 256; i += 128) {
        int bb = i >> 6, dq = i & 63;
        size_t base = (size_t)((bb * EE) + e) * DD + d0 + dq * 4;
        float4 v = *reinterpret_cast<const float4*>(&g_slots_part[0][base]);
#pragma unroll
        for (int p = 1; p < 8; p++) {
            float4 u = *reinterpret_cast<const float4*>(&g_slots_part[p][base]);
            v.x += u.x; v.y += u.y; v.z += u.z; v.w += u.w;
        }
        ssp[(dq * 4 + 0) * 4 + bb] = v.x;
        ssp[(dq * 4 + 1) * 4 + bb] = v.y;
        ssp[(dq * 4 + 2) * 4 + bb] = v.z;
        ssp[(dq * 4 + 3) * 4 + bb] = v.w;
    }
    __syncthreads();

    const float4* ss4 = reinterpret_cast<const float4*>(ssp);
    float4 a0 = make_float4(0.f, 0.f, 0.f, 0.f), a1 = a0, a2 = a0, a3 = a0;
    const float4* wp = reinterpret_cast<const float4*>(w1 + (size_t)e * DD * HH +
                                                      (size_t)d0 * HH) + (j0 >> 2);
#pragma unroll 8
    for (int d = 0; d < 256; d++) {
        float4 wv = __ldcs(wp);
        wp += (HH / 4);
        float4 sv = ss4[d];
        a0.x += sv.x * wv.x; a0.y += sv.x * wv.y; a0.z += sv.x * wv.z; a0.w += sv.x * wv.w;
        a1.x += sv.y * wv.x; a1.y += sv.y * wv.y; a1.z += sv.y * wv.z; a1.w += sv.y * wv.w;
        a2.x += sv.z * wv.x; a2.y += sv.z * wv.y; a2.z += sv.z * wv.z; a2.w += sv.z * wv.w;
        a3.x += sv.w * wv.x; a3.y += sv.w * wv.y; a3.z += sv.w * wv.z; a3.w += sv.w * wv.w;
    }
    *reinterpret_cast<float4*>(&g_h1p[ks][(size_t)(e * 4 + 0) * HH + j0]) = a0;
    *reinterpret_cast<float4*>(&g_h1p[ks][(size_t)(e * 4 + 1) * HH + j0]) = a1;
    *reinterpret_cast<float4*>(&g_h1p[ks][(size_t)(e * 4 + 2) * HH + j0]) = a2;
    *reinterpret_cast<float4*>(&g_h1p[ks][(size_t)(e * 4 + 3) * HH + j0]) = a3;
}

// ---------------- K6: combine softmax + cw metric terms (writes cwT) ----------------
__global__ __launch_bounds__(256) void k_combine() {
    int t = threadIdx.x;
    int w = t >> 5, l = t & 31;
    int bn0 = blockIdx.x * 64;
    __shared__ float cs[64][33];

#pragma unroll
    for (int k = 0; k < 2; k++) {
        int f = t + k * 256;
        int row = f >> 3, q = f & 7;
        float4 v = *reinterpret_cast<const float4*>(&g_logits[(bn0 + row) * EE + q * 4]);
        cs[row][q * 4 + 0] = v.x; cs[row][q * 4 + 1] = v.y;
        cs[row][q * 4 + 2] = v.z; cs[row][q * 4 + 3] = v.w;
    }
    __syncthreads();

    int r = w * 8 + (l >> 2);
    int j = l & 3;
    float v[8];
#pragma unroll
    for (int i = 0; i < 8; i++) v[i] = cs[r][j * 8 + i];

    float m = v[0];
#pragma unroll
    for (int i = 1; i < 8; i++) m = fmaxf(m, v[i]);
    m = fmaxf(m, __shfl_xor_sync(0xffffffffu, m, 1));
    m = fmaxf(m, __shfl_xor_sync(0xffffffffu, m, 2));

    float ex[8], s = 0.f;
#pragma unroll
    for (int i = 0; i < 8; i++) { ex[i] = expf(v[i] - m); s += ex[i]; }
    s += __shfl_xor_sync(0xffffffffu, s, 1);
    s += __shfl_xor_sync(0xffffffffu, s, 2);
    float inv = 1.f / s;

    float cw[8], sq = 0.f, sc = 0.f;
#pragma unroll
    for (int i = 0; i < 8; i++) { cw[i] = ex[i] * inv; sq += cw[i] * cw[i]; sc += cw[i]; }
    sq += __shfl_xor_sync(0xffffffffu, sq, 1);
    sq += __shfl_xor_sync(0xffffffffu, sq, 2);
    sc += __shfl_xor_sync(0xffffffffu, sc, 1);
    sc += __shfl_xor_sync(0xffffffffu, sc, 2);

    int bn = bn0 + r;
    int n = bn & (NN - 1);
    int b = bn >> 10;
#pragma unroll
    for (int i = 0; i < 8; i++)
        g_cwT[((size_t)(b * EE) + j * 8 + i) * NN + n] = cw[i];

    float rs = rsqrtf(sq + PS_EPS);
    float rows = sc * rs;
    if (j == 0) g_cwterm[bn] = rows * rows;
    if (n < EE && j == (n >> 3))
        g_cwdiag[b * EE + n] = cw[n & 7] * rs * rows;
}

// ---------------- K7: metric scalars ----------------
__global__ __launch_bounds__(256) void k_scalars(float* __restrict__ out) {
    __shared__ float red[256];
    int t = threadIdx.x;
    float v;

    v = 0.f; for (int i = t; i < BB * NN; i += 256) v += g_cwterm[i];
    red[t] = v; __syncthreads();
    for (int s = 128; s > 0; s >>= 1) { if (t < s) red[t] += red[t + s]; __syncthreads(); }
    float sumA = red[0]; __syncthreads();

    v = 0.f; for (int i = t; i < BB * EE; i += 256) v += g_cwdiag[i];
    red[t] = v; __syncthreads();
    for (int s = 128; s > 0; s >>= 1) { if (t < s) red[t] += red[t + s]; __syncthreads(); }
    float sumAd = red[0]; __syncthreads();

    v = 0.f; for (int i = t; i < BB * EE; i += 256) v += g_dwterm[i];
    red[t] = v; __syncthreads();
    for (int s = 128; s > 0; s >>= 1) { if (t < s) red[t] += red[t + s]; __syncthreads(); }
    float sumB = red[0]; __syncthreads();

    v = (t < BB) ? g_dwterm[t * EE] : 0.f;
    red[t] = v; __syncthreads();
    for (int s = 128; s > 0; s >>= 1) { if (t < s) red[t] += red[t + s]; __syncthreads(); }
    float sumB0 = red[0];

    if (t == 0) {
        out[(size_t)BB * NN * DD]     = (sumA - sumAd) / (float)(BB * (size_t)NN * (NN - 1));
        out[(size_t)BB * NN * DD + 1] = (sumB - sumB0) / (float)(BB * EE * (EE - 1));
    }
}

// ---------------- K8: w2 pass (h-split 16, gelu fused in staging) ----------------
__global__ __launch_bounds__(128) void k_w2(
    const float* __restrict__ w2, const float* __restrict__ b1) {
    int e = blockIdx.y;
    int dc = blockIdx.x & 1;
    int hs = blockIdx.x >> 1;
    int d0 = dc * 512 + threadIdx.x * 4;
    int h0 = hs * 256;

    __shared__ float4 hsm4[256];
    for (int i = threadIdx.x; i < 4 * 256; i += 128) {
        int b = i >> 8, hh = i & 255;
        size_t hidx = (size_t)(e * 4 + b) * HH + h0 + hh;
        float v = g_h1p[0][hidx] + g_h1p[1][hidx] + g_h1p[2][hidx] + g_h1p[3][hidx] +
                  b1[e * HH + h0 + hh];
        v = v * normcdff(v);
        reinterpret_cast<float*>(hsm4)[hh * 4 + b] = v;
    }
    __syncthreads();

    float4 a0 = make_float4(0.f, 0.f, 0.f, 0.f), a1 = a0, a2 = a0, a3 = a0;
    const float4* wp = reinterpret_cast<const float4*>(
        w2 + (size_t)e * HH * DD + (size_t)h0 * DD) + (d0 >> 2);
#pragma unroll 8
    for (int hh = 0; hh < 256; hh++) {
        float4 wv = __ldcs(wp);
        wp += (DD / 4);
        float4 hv = hsm4[hh];
        a0.x += hv.x * wv.x; a0.y += hv.x * wv.y; a0.z += hv.x * wv.z; a0.w += hv.x * wv.w;
        a1.x += hv.y * wv.x; a1.y += hv.y * wv.y; a1.z += hv.y * wv.z; a1.w += hv.y * wv.w;
        a2.x += hv.z * wv.x; a2.y += hv.z * wv.y; a2.z += hv.z * wv.z; a2.w += hv.z * wv.w;
        a3.x += hv.w * wv.x; a3.y += hv.w * wv.y; a3.z += hv.w * wv.z; a3.w += hv.w * wv.w;
    }
    *reinterpret_cast<float4*>(&g_eo_part[hs][((0 * EE) + e) * DD + d0]) = a0;
    *reinterpret_cast<float4*>(&g_eo_part[hs][((1 * EE) + e) * DD + d0]) = a1;
    *reinterpret_cast<float4*>(&g_eo_part[hs][((2 * EE) + e) * DD + d0]) = a2;
    *reinterpret_cast<float4*>(&g_eo_part[hs][((3 * EE) + e) * DD + d0]) = a3;
}

__global__ __launch_bounds__(256) void k_red_eo(const float* __restrict__ b2) {
    int i = blockIdx.x * 256 + threadIdx.x;
    int d = i & (DD - 1);
    int e = (i >> 10) & (EE - 1);
    float s = b2[e * DD + d];
#pragma unroll
    for (int p = 0; p < 16; p++) s += g_eo_part[p][i];
    g_eo[i] = s;
}

// ---------------- K10: out (register micro-tile GEMM over e) ----------------
// grid (dt=8, nt=32, b=4) = 1024 blocks; thread: 4n x 4d (float4)
__global__ __launch_bounds__(256) void k_out(float* __restrict__ out) {
    int dt = blockIdx.x;
    int nt = blockIdx.y;
    int b = blockIdx.z;
    int t = threadIdx.x;
    int td = t & 31;
    int tn = t >> 5;   // 0..7 -> rows tn*4..tn*4+3
    int d0 = dt * 128;
    int n0 = nt * 32;

    __shared__ float4 eos4[32][32];  // [e][d-quad], 16 KB
    __shared__ float cwTs[32][32];   // [e][nn]

    for (int i = t; i < 1024; i += 256) {
        int e = i >> 5, q = i & 31;
        eos4[e][q] = *reinterpret_cast<const float4*>(
            &g_eo[((b * EE) + e) * DD + d0 + q * 4]);
    }
    for (int i = t; i < 1024; i += 256) {
        int e = i >> 5, nn = i & 31;
        cwTs[e][nn] = g_cwT[((size_t)(b * EE) + e) * NN + n0 + nn];
    }
    __syncthreads();

    float4 a0 = make_float4(0.f, 0.f, 0.f, 0.f), a1 = a0, a2 = a0, a3 = a0;
#pragma unroll
    for (int e = 0; e < 32; e++) {
        float4 ev = eos4[e][td];
        float c0 = cwTs[e][tn * 4 + 0];
        float c1 = cwTs[e][tn * 4 + 1];
        float c2 = cwTs[e][tn * 4 + 2];
        float c3 = cwTs[e][tn * 4 + 3];
        a0.x += c0 * ev.x; a0.y += c0 * ev.y; a0.z += c0 * ev.z; a0.w += c0 * ev.w;
        a1.x += c1 * ev.x; a1.y += c1 * ev.y; a1.z += c1 * ev.z; a1.w += c1 * ev.w;
        a2.x += c2 * ev.x; a2.y += c2 * ev.y; a2.z += c2 * ev.z; a2.w += c2 * ev.w;
        a3.x += c3 * ev.x; a3.y += c3 * ev.y; a3.z += c3 * ev.z; a3.w += c3 * ev.w;
    }
    size_t base = ((size_t)(b * NN) + n0 + tn * 4) * DD + d0 + td * 4;
    *reinterpret_cast<float4*>(&out[base + 0 * DD]) = a0;
    *reinterpret_cast<float4*>(&out[base + 1 * DD]) = a1;
    *reinterpret_cast<float4*>(&out[base + 2 * DD]) = a2;
    *reinterpret_cast<float4*>(&out[base + 3 * DD]) = a3;
}

// ---------------- launch ----------------
extern "C" void kernel_launch(void* const* d_in, const int* in_sizes, int n_in,
                              void* d_out, int out_size) {
    const float* x   = (const float*)d_in[0];
    const float* phi = (const float*)d_in[1];
    const float* kg  = (const float*)d_in[2];
    const float* kb  = (const float*)d_in[3];
    const float* qg  = (const float*)d_in[4];
    const float* qb  = (const float*)d_in[5];
    const float* lg  = (const float*)d_in[6];
    const float* lb  = (const float*)d_in[7];
    const float* sc  = (const float*)d_in[8];
    const float* w1  = (const float*)d_in[9];
    const float* b1  = (const float*)d_in[10];
    const float* w2  = (const float*)d_in[11];
    const float* b2  = (const float*)d_in[12];
    float* out = (float*)d_out;

    k_qnorm<<<EE, 256>>>(phi, qg, qb, lg, lb, sc);
    k_logits<<<dim3(32, 4), 256>>>(x, kg, kb);
    k_dstats<<<BB * EE, 256>>>();
    k_slots<<<dim3(8, 8, 4), 256>>>(x);       // position 4 -> ncu capture
    k_w1<<<dim3(8, 4, 32), 128>>>(w1);
    k_combine<<<64, 256>>>();
    k_scalars<<<1, 256>>>(out);
    k_w2<<<dim3(32, 32), 128>>>(w2, b1);
    k_red_eo<<<512, 256>>>(b2);
    k_out<<<dim3(8, 32, 4), 256>>>(out);
}

// round 5
// speedup vs baseline: 1.0883x; 1.0883x over previous
#include <cuda_runtime.h>
#include <math.h>
#include <stddef.h>

#define BB 4
#define NN 1024
#define DD 1024
#define EE 32
#define HH 4096
#define LN_EPS 1e-5f
#define PS_EPS 1e-9f

// ---------------- scratch (device globals) ----------------
__device__ __align__(16) float g_q[EE * DD];
__device__ __align__(16) float g_logits[BB * NN * EE];    // [b][n][e]
__device__ __align__(16) float g_logitsT[BB * EE * NN];   // [b][e][n]
__device__ __align__(16) float g_cwT[BB * EE * NN];       // combine weights [b][e][n]
__device__ __align__(16) float2 g_minv[BB * EE];          // (max, 1/sum) per (b,e)
__device__ float g_cwterm[BB * NN];
__device__ float g_cwdiag[BB * EE];
__device__ float g_dwterm[BB * EE];
__device__ __align__(16) float g_slots_part[16][BB * EE * DD];
__device__ __align__(16) float g_slots[BB * EE * DD];
__device__ __align__(16) float g_h1p[8][EE * BB * HH];    // pre-gelu partials (k-split 8)
__device__ __align__(16) float g_eo_part[32][BB * EE * DD];
__device__ __align__(16) float g_eo[BB * EE * DD];

// ---------------- K1: q = LayerNorm(phi*qg+qb)*scale ----------------
__global__ __launch_bounds__(256) void k_qnorm(
    const float* __restrict__ phi, const float* __restrict__ qg,
    const float* __restrict__ qb, const float* __restrict__ lng,
    const float* __restrict__ lnb, const float* __restrict__ scale_p) {
    int e = blockIdx.x;
    int t = threadIdx.x;
    __shared__ float v[DD];
    __shared__ float red[256];

    float local = 0.f;
    for (int d = t; d < DD; d += 256) {
        float x = phi[e * DD + d] * qg[d] + qb[d];
        v[d] = x;
        local += x;
    }
    red[t] = local; __syncthreads();
    for (int s = 128; s > 0; s >>= 1) { if (t < s) red[t] += red[t + s]; __syncthreads(); }
    float mean = red[0] * (1.f / DD);
    __syncthreads();

    float lv = 0.f;
    for (int d = t; d < DD; d += 256) { float c = v[d] - mean; lv += c * c; }
    red[t] = lv; __syncthreads();
    for (int s = 128; s > 0; s >>= 1) { if (t < s) red[t] += red[t + s]; __syncthreads(); }
    float var = red[0] * (1.f / DD);
    float rstd = rsqrtf(var + LN_EPS);
    float sc = *scale_p;
    for (int d = t; d < DD; d += 256)
        g_q[e * DD + d] = ((v[d] - mean) * rstd * lng[d] + lnb[d]) * sc;
}

// ---------------- K2: logits (writes both layouts) ----------------
__global__ __launch_bounds__(256) void k_logits(
    const float* __restrict__ x, const float* __restrict__ kg,
    const float* __restrict__ kb) {
    int b = blockIdx.y;
    int n0 = blockIdx.x * 32;
    int t = threadIdx.x;
    int e = t & 31;
    int rq = t >> 5;  // 0..7

    __shared__ float xs[32][33];
    __shared__ float qs[32][33];

    float acc0 = 0.f, acc1 = 0.f, acc2 = 0.f, acc3 = 0.f;
    int c = t & 31;
    for (int dc = 0; dc < DD; dc += 32) {
        for (int r = t >> 5; r < 32; r += 8) {
            int d = dc + c;
            xs[r][c] = x[((size_t)(b * NN) + (n0 + r)) * DD + d] * kg[d] + kb[d];
        }
        for (int r = t >> 5; r < 32; r += 8)
            qs[r][c] = g_q[r * DD + dc + c];
        __syncthreads();
#pragma unroll
        for (int k = 0; k < 32; k++) {
            float qv = qs[e][k];
            acc0 += xs[rq * 4 + 0][k] * qv;
            acc1 += xs[rq * 4 + 1][k] * qv;
            acc2 += xs[rq * 4 + 2][k] * qv;
            acc3 += xs[rq * 4 + 3][k] * qv;
        }
        __syncthreads();
    }
#pragma unroll
    for (int r = 0; r < 4; r++) {
        float a = (r == 0) ? acc0 : (r == 1) ? acc1 : (r == 2) ? acc2 : acc3;
        int n = n0 + rq * 4 + r;
        g_logits[((b * NN) + n) * EE + e] = a;
        g_logitsT[((size_t)(b * EE) + e) * NN + n] = a;
    }
}

// ---------------- K3: dispatch softmax stats per (b,e) + dw metric ----------------
__global__ __launch_bounds__(256) void k_dstats() {
    int be = blockIdx.x;
    int t = threadIdx.x;
    __shared__ float red[256];

    const float4* L = reinterpret_cast<const float4*>(g_logitsT + (size_t)be * NN);
    float4 v = L[t];

    float m = fmaxf(fmaxf(v.x, v.y), fmaxf(v.z, v.w));
    red[t] = m; __syncthreads();
    for (int s = 128; s > 0; s >>= 1) { if (t < s) red[t] = fmaxf(red[t], red[t + s]); __syncthreads(); }
    m = red[0]; __syncthreads();

    float ex0 = expf(v.x - m), ex1 = expf(v.y - m), ex2 = expf(v.z - m), ex3 = expf(v.w - m);
    red[t] = ex0 + ex1 + ex2 + ex3; __syncthreads();
    for (int s = 128; s > 0; s >>= 1) { if (t < s) red[t] += red[t + s]; __syncthreads(); }
    float ssum = red[0]; __syncthreads();

    red[t] = ex0 * ex0 + ex1 * ex1 + ex2 * ex2 + ex3 * ex3; __syncthreads();
    for (int s = 128; s > 0; s >>= 1) { if (t < s) red[t] += red[t + s]; __syncthreads(); }

    if (t == 0) {
        float ssq = red[0];
        float inv = 1.f / ssum;
        g_minv[be] = make_float2(m, inv);
        float wsq = ssq * inv * inv;
        float rs = rsqrtf(wsq + PS_EPS);
        float rn = (ssum * inv) * rs;
        g_dwterm[be] = rn * rn;
    }
}

// ---------------- K4: slots partials (register micro-tile GEMM) ----------------
// grid (dt=8, ns=16, b=4) = 512 blocks; thread: 4e x 4d (float4), 16 accs
__global__ __launch_bounds__(256) void k_slots(const float* __restrict__ x) {
    int dt = blockIdx.x;
    int ns = blockIdx.y;
    int b = blockIdx.z;
    int t = threadIdx.x;
    int td = t & 31;   // d-quad
    int te = t >> 5;   // 0..7 -> experts te*4..te*4+3
    int d0 = dt * 128;
    int n0 = ns * 64;

    __shared__ float4 xs4[32][32];   // [nn][d-quad], 16 KB
    __shared__ float dwsT[32][33];   // [e][nn]

    float4 a0 = make_float4(0.f, 0.f, 0.f, 0.f), a1 = a0, a2 = a0, a3 = a0;

    for (int c = 0; c < 2; c++) {
        int nc = n0 + c * 32;
        __syncthreads();
        for (int i = t; i < 1024; i += 256) {
            int row = i >> 5, q = i & 31;
            xs4[row][q] = *reinterpret_cast<const float4*>(
                x + ((size_t)(b * NN) + nc + row) * DD + d0 + q * 4);
        }
        for (int i = t; i < 1024; i += 256) {
            int e = i >> 5, nn = i & 31;
            float2 mi = g_minv[b * EE + e];
            float lv = g_logitsT[((size_t)(b * EE) + e) * NN + nc + nn];
            dwsT[e][nn] = expf(lv - mi.x) * mi.y;
        }
        __syncthreads();
#pragma unroll
        for (int k = 0; k < 32; k++) {
            float4 xv = xs4[k][td];
            float w0 = dwsT[te * 4 + 0][k];
            float w1 = dwsT[te * 4 + 1][k];
            float w2 = dwsT[te * 4 + 2][k];
            float w3 = dwsT[te * 4 + 3][k];
            a0.x += w0 * xv.x; a0.y += w0 * xv.y; a0.z += w0 * xv.z; a0.w += w0 * xv.w;
            a1.x += w1 * xv.x; a1.y += w1 * xv.y; a1.z += w1 * xv.z; a1.w += w1 * xv.w;
            a2.x += w2 * xv.x; a2.y += w2 * xv.y; a2.z += w2 * xv.z; a2.w += w2 * xv.w;
            a3.x += w3 * xv.x; a3.y += w3 * xv.y; a3.z += w3 * xv.z; a3.w += w3 * xv.w;
        }
    }
    size_t base = ((size_t)(b * EE) + te * 4) * DD + d0 + td * 4;
    *reinterpret_cast<float4*>(&g_slots_part[ns][base + 0 * DD]) = a0;
    *reinterpret_cast<float4*>(&g_slots_part[ns][base + 1 * DD]) = a1;
    *reinterpret_cast<float4*>(&g_slots_part[ns][base + 2 * DD]) = a2;
    *reinterpret_cast<float4*>(&g_slots_part[ns][base + 3 * DD]) = a3;
}

// ---------------- K4b: reduce slot partials ----------------
__global__ __launch_bounds__(256) void k_red_slots() {
    int i = blockIdx.x * 256 + threadIdx.x;  // 32768 float4s
    const float4* p0 = reinterpret_cast<const float4*>(g_slots_part[0]);
    float4 v = p0[i];
#pragma unroll
    for (int p = 1; p < 16; p++) {
        float4 u = reinterpret_cast<const float4*>(g_slots_part[p])[i];
        v.x += u.x; v.y += u.y; v.z += u.z; v.w += u.w;
    }
    reinterpret_cast<float4*>(g_slots)[i] = v;
}

// ---------------- K5: w1 pass (k-split 8) ----------------
// grid (jc=8, ks=8, e=32) = 2048 blocks, 128 threads
__global__ __launch_bounds__(128) void k_w1(const float* __restrict__ w1) {
    int e = blockIdx.z;
    int ks = blockIdx.y;
    int j0 = blockIdx.x * 512 + threadIdx.x * 4;
    int d0 = ks * 128;

    __shared__ float ssp[128 * 4];  // [d][b]
    if (threadIdx.x < 128) {
        int d = threadIdx.x;
#pragma unroll
        for (int bb = 0; bb < 4; bb++)
            ssp[d * 4 + bb] = g_slots[(size_t)((bb * EE) + e) * DD + d0 + d];
    }
    __syncthreads();

    const float4* ss4 = reinterpret_cast<const float4*>(ssp);
    float4 a0 = make_float4(0.f, 0.f, 0.f, 0.f), a1 = a0, a2 = a0, a3 = a0;
    const float4* wp = reinterpret_cast<const float4*>(w1 + (size_t)e * DD * HH +
                                                      (size_t)d0 * HH) + (j0 >> 2);
#pragma unroll 8
    for (int d = 0; d < 128; d++) {
        float4 wv = __ldcs(wp);
        wp += (HH / 4);
        float4 sv = ss4[d];
        a0.x += sv.x * wv.x; a0.y += sv.x * wv.y; a0.z += sv.x * wv.z; a0.w += sv.x * wv.w;
        a1.x += sv.y * wv.x; a1.y += sv.y * wv.y; a1.z += sv.y * wv.z; a1.w += sv.y * wv.w;
        a2.x += sv.z * wv.x; a2.y += sv.z * wv.y; a2.z += sv.z * wv.z; a2.w += sv.z * wv.w;
        a3.x += sv.w * wv.x; a3.y += sv.w * wv.y; a3.z += sv.w * wv.z; a3.w += sv.w * wv.w;
    }
    *reinterpret_cast<float4*>(&g_h1p[ks][(size_t)(e * 4 + 0) * HH + j0]) = a0;
    *reinterpret_cast<float4*>(&g_h1p[ks][(size_t)(e * 4 + 1) * HH + j0]) = a1;
    *reinterpret_cast<float4*>(&g_h1p[ks][(size_t)(e * 4 + 2) * HH + j0]) = a2;
    *reinterpret_cast<float4*>(&g_h1p[ks][(size_t)(e * 4 + 3) * HH + j0]) = a3;
}

// ---------------- K6: combine softmax + cw metric terms (writes cwT) ----------------
__global__ __launch_bounds__(256) void k_combine() {
    int t = threadIdx.x;
    int w = t >> 5, l = t & 31;
    int bn0 = blockIdx.x * 64;
    __shared__ float cs[64][33];

#pragma unroll
    for (int k = 0; k < 2; k++) {
        int f = t + k * 256;
        int row = f >> 3, q = f & 7;
        float4 v = *reinterpret_cast<const float4*>(&g_logits[(bn0 + row) * EE + q * 4]);
        cs[row][q * 4 + 0] = v.x; cs[row][q * 4 + 1] = v.y;
        cs[row][q * 4 + 2] = v.z; cs[row][q * 4 + 3] = v.w;
    }
    __syncthreads();

    int r = w * 8 + (l >> 2);
    int j = l & 3;
    float v[8];
#pragma unroll
    for (int i = 0; i < 8; i++) v[i] = cs[r][j * 8 + i];

    float m = v[0];
#pragma unroll
    for (int i = 1; i < 8; i++) m = fmaxf(m, v[i]);
    m = fmaxf(m, __shfl_xor_sync(0xffffffffu, m, 1));
    m = fmaxf(m, __shfl_xor_sync(0xffffffffu, m, 2));

    float ex[8], s = 0.f;
#pragma unroll
    for (int i = 0; i < 8; i++) { ex[i] = expf(v[i] - m); s += ex[i]; }
    s += __shfl_xor_sync(0xffffffffu, s, 1);
    s += __shfl_xor_sync(0xffffffffu, s, 2);
    float inv = 1.f / s;

    float cw[8], sq = 0.f, sc = 0.f;
#pragma unroll
    for (int i = 0; i < 8; i++) { cw[i] = ex[i] * inv; sq += cw[i] * cw[i]; sc += cw[i]; }
    sq += __shfl_xor_sync(0xffffffffu, sq, 1);
    sq += __shfl_xor_sync(0xffffffffu, sq, 2);
    sc += __shfl_xor_sync(0xffffffffu, sc, 1);
    sc += __shfl_xor_sync(0xffffffffu, sc, 2);

    int bn = bn0 + r;
    int n = bn & (NN - 1);
    int b = bn >> 10;
#pragma unroll
    for (int i = 0; i < 8; i++)
        g_cwT[((size_t)(b * EE) + j * 8 + i) * NN + n] = cw[i];

    float rs = rsqrtf(sq + PS_EPS);
    float rows = sc * rs;
    if (j == 0) g_cwterm[bn] = rows * rows;
    if (n < EE && j == (n >> 3))
        g_cwdiag[b * EE + n] = cw[n & 7] * rs * rows;
}

// ---------------- K7: metric scalars ----------------
__global__ __launch_bounds__(256) void k_scalars(float* __restrict__ out) {
    __shared__ float red[256];
    int t = threadIdx.x;
    float v;

    v = 0.f; for (int i = t; i < BB * NN; i += 256) v += g_cwterm[i];
    red[t] = v; __syncthreads();
    for (int s = 128; s > 0; s >>= 1) { if (t < s) red[t] += red[t + s]; __syncthreads(); }
    float sumA = red[0]; __syncthreads();

    v = 0.f; for (int i = t; i < BB * EE; i += 256) v += g_cwdiag[i];
    red[t] = v; __syncthreads();
    for (int s = 128; s > 0; s >>= 1) { if (t < s) red[t] += red[t + s]; __syncthreads(); }
    float sumAd = red[0]; __syncthreads();

    v = 0.f; for (int i = t; i < BB * EE; i += 256) v += g_dwterm[i];
    red[t] = v; __syncthreads();
    for (int s = 128; s > 0; s >>= 1) { if (t < s) red[t] += red[t + s]; __syncthreads(); }
    float sumB = red[0]; __syncthreads();

    v = (t < BB) ? g_dwterm[t * EE] : 0.f;
    red[t] = v; __syncthreads();
    for (int s = 128; s > 0; s >>= 1) { if (t < s) red[t] += red[t + s]; __syncthreads(); }
    float sumB0 = red[0];

    if (t == 0) {
        out[(size_t)BB * NN * DD]     = (sumA - sumAd) / (float)(BB * (size_t)NN * (NN - 1));
        out[(size_t)BB * NN * DD + 1] = (sumB - sumB0) / (float)(BB * EE * (EE - 1));
    }
}

// ---------------- K8: w2 pass (h-split 32, gelu fused in staging) ----------------
// grid (x = dc(2) x hs(32) = 64, e=32) = 2048 blocks, 128 threads
__global__ __launch_bounds__(128) void k_w2(
    const float* __restrict__ w2, const float* __restrict__ b1) {
    int e = blockIdx.y;
    int dc = blockIdx.x & 1;
    int hs = blockIdx.x >> 1;
    int d0 = dc * 512 + threadIdx.x * 4;
    int h0 = hs * 128;

    __shared__ float4 hsm4[128];  // [hh] -> (b0,b1,b2,b3)
    for (int i = threadIdx.x; i < 4 * 128; i += 128) {
        int b = i >> 7, hh = i & 127;
        size_t hidx = (size_t)(e * 4 + b) * HH + h0 + hh;
        float v = b1[e * HH + h0 + hh];
#pragma unroll
        for (int p = 0; p < 8; p++) v += g_h1p[p][hidx];
        v = v * normcdff(v);
        reinterpret_cast<float*>(hsm4)[hh * 4 + b] = v;
    }
    __syncthreads();

    float4 a0 = make_float4(0.f, 0.f, 0.f, 0.f), a1 = a0, a2 = a0, a3 = a0;
    const float4* wp = reinterpret_cast<const float4*>(
        w2 + (size_t)e * HH * DD + (size_t)h0 * DD) + (d0 >> 2);
#pragma unroll 8
    for (int hh = 0; hh < 128; hh++) {
        float4 wv = __ldcs(wp);
        wp += (DD / 4);
        float4 hv = hsm4[hh];
        a0.x += hv.x * wv.x; a0.y += hv.x * wv.y; a0.z += hv.x * wv.z; a0.w += hv.x * wv.w;
        a1.x += hv.y * wv.x; a1.y += hv.y * wv.y; a1.z += hv.y * wv.z; a1.w += hv.y * wv.w;
        a2.x += hv.z * wv.x; a2.y += hv.z * wv.y; a2.z += hv.z * wv.z; a2.w += hv.z * wv.w;
        a3.x += hv.w * wv.x; a3.y += hv.w * wv.y; a3.z += hv.w * wv.z; a3.w += hv.w * wv.w;
    }
    *reinterpret_cast<float4*>(&g_eo_part[hs][((0 * EE) + e) * DD + d0]) = a0;
    *reinterpret_cast<float4*>(&g_eo_part[hs][((1 * EE) + e) * DD + d0]) = a1;
    *reinterpret_cast<float4*>(&g_eo_part[hs][((2 * EE) + e) * DD + d0]) = a2;
    *reinterpret_cast<float4*>(&g_eo_part[hs][((3 * EE) + e) * DD + d0]) = a3;
}

__global__ __launch_bounds__(256) void k_red_eo(const float* __restrict__ b2) {
    int i = blockIdx.x * 256 + threadIdx.x;
    int d = i & (DD - 1);
    int e = (i >> 10) & (EE - 1);
    float s = b2[e * DD + d];
#pragma unroll
    for (int p = 0; p < 32; p++) s += g_eo_part[p][i];
    g_eo[i] = s;
}

// ---------------- K10: out (register micro-tile GEMM over e) ----------------
// grid (dt=8, nt=32, b=4) = 1024 blocks; thread: 4n x 4d (float4)
__global__ __launch_bounds__(256) void k_out(float* __restrict__ out) {
    int dt = blockIdx.x;
    int nt = blockIdx.y;
    int b = blockIdx.z;
    int t = threadIdx.x;
    int td = t & 31;
    int tn = t >> 5;   // 0..7 -> rows tn*4..tn*4+3
    int d0 = dt * 128;
    int n0 = nt * 32;

    __shared__ float4 eos4[32][32];  // [e][d-quad], 16 KB
    __shared__ float cwTs[32][32];   // [e][nn]

    for (int i = t; i < 1024; i += 256) {
        int e = i >> 5, q = i & 31;
        eos4[e][q] = *reinterpret_cast<const float4*>(
            &g_eo[((b * EE) + e) * DD + d0 + q * 4]);
    }
    for (int i = t; i < 1024; i += 256) {
        int e = i >> 5, nn = i & 31;
        cwTs[e][nn] = g_cwT[((size_t)(b * EE) + e) * NN + n0 + nn];
    }
    __syncthreads();

    float4 a0 = make_float4(0.f, 0.f, 0.f, 0.f), a1 = a0, a2 = a0, a3 = a0;
#pragma unroll
    for (int e = 0; e < 32; e++) {
        float4 ev = eos4[e][td];
        float c0 = cwTs[e][tn * 4 + 0];
        float c1 = cwTs[e][tn * 4 + 1];
        float c2 = cwTs[e][tn * 4 + 2];
        float c3 = cwTs[e][tn * 4 + 3];
        a0.x += c0 * ev.x; a0.y += c0 * ev.y; a0.z += c0 * ev.z; a0.w += c0 * ev.w;
        a1.x += c1 * ev.x; a1.y += c1 * ev.y; a1.z += c1 * ev.z; a1.w += c1 * ev.w;
        a2.x += c2 * ev.x; a2.y += c2 * ev.y; a2.z += c2 * ev.z; a2.w += c2 * ev.w;
        a3.x += c3 * ev.x; a3.y += c3 * ev.y; a3.z += c3 * ev.z; a3.w += c3 * ev.w;
    }
    size_t base = ((size_t)(b * NN) + n0 + tn * 4) * DD + d0 + td * 4;
    *reinterpret_cast<float4*>(&out[base + 0 * DD]) = a0;
    *reinterpret_cast<float4*>(&out[base + 1 * DD]) = a1;
    *reinterpret_cast<float4*>(&out[base + 2 * DD]) = a2;
    *reinterpret_cast<float4*>(&out[base + 3 * DD]) = a3;
}

// ---------------- launch ----------------
extern "C" void kernel_launch(void* const* d_in, const int* in_sizes, int n_in,
                              void* d_out, int out_size) {
    const float* x   = (const float*)d_in[0];
    const float* phi = (const float*)d_in[1];
    const float* kg  = (const float*)d_in[2];
    const float* kb  = (const float*)d_in[3];
    const float* qg  = (const float*)d_in[4];
    const float* qb  = (const float*)d_in[5];
    const float* lg  = (const float*)d_in[6];
    const float* lb  = (const float*)d_in[7];
    const float* sc  = (const float*)d_in[8];
    const float* w1  = (const float*)d_in[9];
    const float* b1  = (const float*)d_in[10];
    const float* w2  = (const float*)d_in[11];
    const float* b2  = (const float*)d_in[12];
    float* out = (float*)d_out;

    k_qnorm<<<EE, 256>>>(phi, qg, qb, lg, lb, sc);
    k_logits<<<dim3(32, 4), 256>>>(x, kg, kb);
    k_dstats<<<BB * EE, 256>>>();
    k_slots<<<dim3(8, 16, 4), 256>>>(x);      // position 4 -> ncu capture
    k_red_slots<<<128, 256>>>();
    k_w1<<<dim3(8, 8, 32), 128>>>(w1);
    k_combine<<<64, 256>>>();
    k_scalars<<<1, 256>>>(out);
    k_w2<<<dim3(64, 32), 128>>>(w2, b1);
    k_red_eo<<<512, 256>>>(b2);
    k_out<<<dim3(8, 32, 4), 256>>>(out);
}

// round 7
// speedup vs baseline: 1.3853x; 1.2729x over previous
#include <cuda_runtime.h>
#include <math.h>
#include <stddef.h>

#define BB 4
#define NN 1024
#define DD 1024
#define EE 32
#define HH 4096
#define LN_EPS 1e-5f
#define PS_EPS 1e-9f

// ---------------- scratch (device globals) ----------------
__device__ __align__(16) float g_q[EE * DD];
__device__ __align__(16) float g_logits[BB * NN * EE];    // [b][n][e]
__device__ __align__(16) float g_logitsT[BB * EE * NN];   // [b][e][n]
__device__ __align__(16) float g_cw[BB * NN * EE];        // combine weights [b][n][e]
__device__ __align__(16) float2 g_minv[BB * EE];          // (max, 1/sum) per (b,e)
__device__ float g_cwterm[BB * NN];
__device__ float g_cwdiag[BB * EE];
__device__ float g_dwterm[BB * EE];
__device__ __align__(16) float g_slots_part[16][BB * EE * DD];
__device__ __align__(16) float g_slots[BB * EE * DD];
__device__ __align__(16) float g_h1p[8][EE * BB * HH];    // pre-gelu partials (k-split 8)
__device__ __align__(16) float g_eo_part[32][BB * EE * DD];
__device__ __align__(16) float g_eo[BB * EE * DD];

__device__ __forceinline__ float fold_dq(float v) {
    v += __shfl_xor_sync(0xffffffffu, v, 8);
    v += __shfl_xor_sync(0xffffffffu, v, 16);
    return v;
}

// ---------------- K1: q = LayerNorm(phi*qg+qb)*scale ----------------
__global__ __launch_bounds__(256) void k_qnorm(
    const float* __restrict__ phi, const float* __restrict__ qg,
    const float* __restrict__ qb, const float* __restrict__ lng,
    const float* __restrict__ lnb, const float* __restrict__ scale_p) {
    int e = blockIdx.x;
    int t = threadIdx.x;
    __shared__ float v[DD];
    __shared__ float red[256];

    float local = 0.f;
    for (int d = t; d < DD; d += 256) {
        float x = phi[e * DD + d] * qg[d] + qb[d];
        v[d] = x;
        local += x;
    }
    red[t] = local; __syncthreads();
    for (int s = 128; s > 0; s >>= 1) { if (t < s) red[t] += red[t + s]; __syncthreads(); }
    float mean = red[0] * (1.f / DD);
    __syncthreads();

    float lv = 0.f;
    for (int d = t; d < DD; d += 256) { float c = v[d] - mean; lv += c * c; }
    red[t] = lv; __syncthreads();
    for (int s = 128; s > 0; s >>= 1) { if (t < s) red[t] += red[t + s]; __syncthreads(); }
    float var = red[0] * (1.f / DD);
    float rstd = rsqrtf(var + LN_EPS);
    float sc = *scale_p;
    for (int d = t; d < DD; d += 256)
        g_q[e * DD + d] = ((v[d] - mean) * rstd * lng[d] + lnb[d]) * sc;
}

// ---------------- K2: logits v3 (register micro-tile, D split 4-way in-warp) ----------------
// grid (nt=32, b=4) = 128 blocks, 256 threads.
// t = eq*32 + dq*8 + nq: eq=warp (4 e), dq=D-quarter within chunk, nq=4 n.
__global__ __launch_bounds__(256) void k_logits(
    const float* __restrict__ x, const float* __restrict__ kg,
    const float* __restrict__ kb) {
    int b = blockIdx.y;
    int n0 = blockIdx.x * 32;
    int t = threadIdx.x;
    int eq = t >> 5;         // 0..7
    int dq = (t >> 3) & 3;   // 0..3
    int nq = t & 7;          // 0..7

    __shared__ float xsT[128][36];  // [d within chunk][n]
    __shared__ float qsT[128][36];  // [d within chunk][e]

    // staging thread roles
    int w = t >> 5, l = t & 31;
    int dseg = (w & 3) * 32;        // d-segment within 128-chunk
    int half = (w >> 2) * 16;       // n-half / e-half

    float4 aN0 = make_float4(0.f, 0.f, 0.f, 0.f), aN1 = aN0, aN2 = aN0, aN3 = aN0;

    for (int c = 0; c < 8; c++) {
        int dd0 = dseg + l;              // 0..127
        int dglob = c * 128 + dd0;
        float kgv = kg[dglob], kbv = kb[dglob];
        __syncthreads();
#pragma unroll
        for (int i = 0; i < 16; i++) {
            int n = half + i;
            xsT[dd0][n] = x[((size_t)(b * NN) + n0 + n) * DD + dglob] * kgv + kbv;
            qsT[dd0][n] = g_q[n * DD + dglob];   // n here doubles as e row
        }
        __syncthreads();
#pragma unroll
        for (int k = 0; k < 32; k++) {
            int dd = dq * 32 + k;
            float4 xv = *reinterpret_cast<const float4*>(&xsT[dd][nq * 4]);
            float4 qv = *reinterpret_cast<const float4*>(&qsT[dd][eq * 4]);
            aN0.x += xv.x * qv.x; aN0.y += xv.x * qv.y; aN0.z += xv.x * qv.z; aN0.w += xv.x * qv.w;
            aN1.x += xv.y * qv.x; aN1.y += xv.y * qv.y; aN1.z += xv.y * qv.z; aN1.w += xv.y * qv.w;
            aN2.x += xv.z * qv.x; aN2.y += xv.z * qv.y; aN2.z += xv.z * qv.z; aN2.w += xv.z * qv.w;
            aN3.x += xv.w * qv.x; aN3.y += xv.w * qv.y; aN3.z += xv.w * qv.z; aN3.w += xv.w * qv.w;
        }
    }

    // fold dq (lane bits 3,4) — explicit per-component shuffles (NO pointer aliasing)
    aN0.x = fold_dq(aN0.x); aN0.y = fold_dq(aN0.y); aN0.z = fold_dq(aN0.z); aN0.w = fold_dq(aN0.w);
    aN1.x = fold_dq(aN1.x); aN1.y = fold_dq(aN1.y); aN1.z = fold_dq(aN1.z); aN1.w = fold_dq(aN1.w);
    aN2.x = fold_dq(aN2.x); aN2.y = fold_dq(aN2.y); aN2.z = fold_dq(aN2.z); aN2.w = fold_dq(aN2.w);
    aN3.x = fold_dq(aN3.x); aN3.y = fold_dq(aN3.y); aN3.z = fold_dq(aN3.z); aN3.w = fold_dq(aN3.w);

    if (dq == 0) {
        float4 accs[4] = {aN0, aN1, aN2, aN3};
#pragma unroll
        for (int i = 0; i < 4; i++) {
            int n = n0 + nq * 4 + i;
            *reinterpret_cast<float4*>(&g_logits[((b * NN) + n) * EE + eq * 4]) = accs[i];
            g_logitsT[((size_t)(b * EE) + eq * 4 + 0) * NN + n] = accs[i].x;
            g_logitsT[((size_t)(b * EE) + eq * 4 + 1) * NN + n] = accs[i].y;
            g_logitsT[((size_t)(b * EE) + eq * 4 + 2) * NN + n] = accs[i].z;
            g_logitsT[((size_t)(b * EE) + eq * 4 + 3) * NN + n] = accs[i].w;
        }
    }
}

// ---------------- K3: dispatch softmax stats per (b,e) + dw metric ----------------
__global__ __launch_bounds__(256) void k_dstats() {
    int be = blockIdx.x;
    int t = threadIdx.x;
    __shared__ float red[256];

    const float4* L = reinterpret_cast<const float4*>(g_logitsT + (size_t)be * NN);
    float4 v = L[t];

    float m = fmaxf(fmaxf(v.x, v.y), fmaxf(v.z, v.w));
    red[t] = m; __syncthreads();
    for (int s = 128; s > 0; s >>= 1) { if (t < s) red[t] = fmaxf(red[t], red[t + s]); __syncthreads(); }
    m = red[0]; __syncthreads();

    float ex0 = expf(v.x - m), ex1 = expf(v.y - m), ex2 = expf(v.z - m), ex3 = expf(v.w - m);
    red[t] = ex0 + ex1 + ex2 + ex3; __syncthreads();
    for (int s = 128; s > 0; s >>= 1) { if (t < s) red[t] += red[t + s]; __syncthreads(); }
    float ssum = red[0]; __syncthreads();

    red[t] = ex0 * ex0 + ex1 * ex1 + ex2 * ex2 + ex3 * ex3; __syncthreads();
    for (int s = 128; s > 0; s >>= 1) { if (t < s) red[t] += red[t + s]; __syncthreads(); }

    if (t == 0) {
        float ssq = red[0];
        float inv = 1.f / ssum;
        g_minv[be] = make_float2(m, inv);
        float wsq = ssq * inv * inv;
        float rs = rsqrtf(wsq + PS_EPS);
        float rn = (ssum * inv) * rs;
        g_dwterm[be] = rn * rn;
    }
}

// ---------------- K4: slots partials (register micro-tile GEMM) ----------------
// grid (dt=8, ns=16, b=4) = 512 blocks; thread: 4e x 4d (float4), 16 accs
__global__ __launch_bounds__(256) void k_slots(const float* __restrict__ x) {
    int dt = blockIdx.x;
    int ns = blockIdx.y;
    int b = blockIdx.z;
    int t = threadIdx.x;
    int td = t & 31;   // d-quad
    int te = t >> 5;   // 0..7 -> experts te*4..te*4+3
    int d0 = dt * 128;
    int n0 = ns * 64;

    __shared__ float4 xs4[32][32];   // [nn][d-quad], 16 KB
    __shared__ float dwsT[32][33];   // [e][nn]

    float4 a0 = make_float4(0.f, 0.f, 0.f, 0.f), a1 = a0, a2 = a0, a3 = a0;

    for (int c = 0; c < 2; c++) {
        int nc = n0 + c * 32;
        __syncthreads();
        for (int i = t; i < 1024; i += 256) {
            int row = i >> 5, q = i & 31;
            xs4[row][q] = *reinterpret_cast<const float4*>(
                x + ((size_t)(b * NN) + nc + row) * DD + d0 + q * 4);
        }
        for (int i = t; i < 1024; i += 256) {
            int e = i >> 5, nn = i & 31;
            float2 mi = g_minv[b * EE + e];
            float lv = g_logitsT[((size_t)(b * EE) + e) * NN + nc + nn];
            dwsT[e][nn] = expf(lv - mi.x) * mi.y;
        }
        __syncthreads();
#pragma unroll
        for (int k = 0; k < 32; k++) {
            float4 xv = xs4[k][td];
            float w0 = dwsT[te * 4 + 0][k];
            float w1 = dwsT[te * 4 + 1][k];
            float w2 = dwsT[te * 4 + 2][k];
            float w3 = dwsT[te * 4 + 3][k];
            a0.x += w0 * xv.x; a0.y += w0 * xv.y; a0.z += w0 * xv.z; a0.w += w0 * xv.w;
            a1.x += w1 * xv.x; a1.y += w1 * xv.y; a1.z += w1 * xv.z; a1.w += w1 * xv.w;
            a2.x += w2 * xv.x; a2.y += w2 * xv.y; a2.z += w2 * xv.z; a2.w += w2 * xv.w;
            a3.x += w3 * xv.x; a3.y += w3 * xv.y; a3.z += w3 * xv.z; a3.w += w3 * xv.w;
        }
    }
    size_t base = ((size_t)(b * EE) + te * 4) * DD + d0 + td * 4;
    *reinterpret_cast<float4*>(&g_slots_part[ns][base + 0 * DD]) = a0;
    *reinterpret_cast<float4*>(&g_slots_part[ns][base + 1 * DD]) = a1;
    *reinterpret_cast<float4*>(&g_slots_part[ns][base + 2 * DD]) = a2;
    *reinterpret_cast<float4*>(&g_slots_part[ns][base + 3 * DD]) = a3;
}

// ---------------- K4b: reduce slot partials ----------------
__global__ __launch_bounds__(256) void k_red_slots() {
    int i = blockIdx.x * 256 + threadIdx.x;  // 32768 float4s
    const float4* p0 = reinterpret_cast<const float4*>(g_slots_part[0]);
    float4 v = p0[i];
#pragma unroll
    for (int p = 1; p < 16; p++) {
        float4 u = reinterpret_cast<const float4*>(g_slots_part[p])[i];
        v.x += u.x; v.y += u.y; v.z += u.z; v.w += u.w;
    }
    reinterpret_cast<float4*>(g_slots)[i] = v;
}

// ---------------- K5: w1 pass (k-split 8) ----------------
// grid (jc=8, ks=8, e=32) = 2048 blocks, 128 threads
__global__ __launch_bounds__(128) void k_w1(const float* __restrict__ w1) {
    int e = blockIdx.z;
    int ks = blockIdx.y;
    int j0 = blockIdx.x * 512 + threadIdx.x * 4;
    int d0 = ks * 128;

    __shared__ float ssp[128 * 4];  // [d][b]
    {
        int d = threadIdx.x;
#pragma unroll
        for (int bb = 0; bb < 4; bb++)
            ssp[d * 4 + bb] = g_slots[(size_t)((bb * EE) + e) * DD + d0 + d];
    }
    __syncthreads();

    const float4* ss4 = reinterpret_cast<const float4*>(ssp);
    float4 a0 = make_float4(0.f, 0.f, 0.f, 0.f), a1 = a0, a2 = a0, a3 = a0;
    const float4* wp = reinterpret_cast<const float4*>(w1 + (size_t)e * DD * HH +
                                                      (size_t)d0 * HH) + (j0 >> 2);
#pragma unroll 8
    for (int d = 0; d < 128; d++) {
        float4 wv = __ldcs(wp);
        wp += (HH / 4);
        float4 sv = ss4[d];
        a0.x += sv.x * wv.x; a0.y += sv.x * wv.y; a0.z += sv.x * wv.z; a0.w += sv.x * wv.w;
        a1.x += sv.y * wv.x; a1.y += sv.y * wv.y; a1.z += sv.y * wv.z; a1.w += sv.y * wv.w;
        a2.x += sv.z * wv.x; a2.y += sv.z * wv.y; a2.z += sv.z * wv.z; a2.w += sv.z * wv.w;
        a3.x += sv.w * wv.x; a3.y += sv.w * wv.y; a3.z += sv.w * wv.z; a3.w += sv.w * wv.w;
    }
    *reinterpret_cast<float4*>(&g_h1p[ks][(size_t)(e * 4 + 0) * HH + j0]) = a0;
    *reinterpret_cast<float4*>(&g_h1p[ks][(size_t)(e * 4 + 1) * HH + j0]) = a1;
    *reinterpret_cast<float4*>(&g_h1p[ks][(size_t)(e * 4 + 2) * HH + j0]) = a2;
    *reinterpret_cast<float4*>(&g_h1p[ks][(size_t)(e * 4 + 3) * HH + j0]) = a3;
}

// ---------------- K6: combine softmax + cw metric terms ----------------
__global__ __launch_bounds__(256) void k_combine() {
    int t = threadIdx.x;
    int w = t >> 5, l = t & 31;
    int bn0 = blockIdx.x * 64;
    __shared__ float cs[64][33];

#pragma unroll
    for (int k = 0; k < 2; k++) {
        int f = t + k * 256;
        int row = f >> 3, q = f & 7;
        float4 v = *reinterpret_cast<const float4*>(&g_logits[(bn0 + row) * EE + q * 4]);
        cs[row][q * 4 + 0] = v.x; cs[row][q * 4 + 1] = v.y;
        cs[row][q * 4 + 2] = v.z; cs[row][q * 4 + 3] = v.w;
    }
    __syncthreads();

    int r = w * 8 + (l >> 2);
    int j = l & 3;
    float v[8];
#pragma unroll
    for (int i = 0; i < 8; i++) v[i] = cs[r][j * 8 + i];

    float m = v[0];
#pragma unroll
    for (int i = 1; i < 8; i++) m = fmaxf(m, v[i]);
    m = fmaxf(m, __shfl_xor_sync(0xffffffffu, m, 1));
    m = fmaxf(m, __shfl_xor_sync(0xffffffffu, m, 2));

    float ex[8], s = 0.f;
#pragma unroll
    for (int i = 0; i < 8; i++) { ex[i] = expf(v[i] - m); s += ex[i]; }
    s += __shfl_xor_sync(0xffffffffu, s, 1);
    s += __shfl_xor_sync(0xffffffffu, s, 2);
    float inv = 1.f / s;

    float cw[8], sq = 0.f, sc = 0.f;
#pragma unroll
    for (int i = 0; i < 8; i++) { cw[i] = ex[i] * inv; sq += cw[i] * cw[i]; sc += cw[i]; }
    sq += __shfl_xor_sync(0xffffffffu, sq, 1);
    sq += __shfl_xor_sync(0xffffffffu, sq, 2);
    sc += __shfl_xor_sync(0xffffffffu, sc, 1);
    sc += __shfl_xor_sync(0xffffffffu, sc, 2);

    int bn = bn0 + r;
    *reinterpret_cast<float4*>(&g_cw[bn * EE + j * 8]) =
        make_float4(cw[0], cw[1], cw[2], cw[3]);
    *reinterpret_cast<float4*>(&g_cw[bn * EE + j * 8 + 4]) =
        make_float4(cw[4], cw[5], cw[6], cw[7]);

    float rs = rsqrtf(sq + PS_EPS);
    float rows = sc * rs;
    int n = bn & (NN - 1);
    int b = bn >> 10;
    if (j == 0) g_cwterm[bn] = rows * rows;
    if (n < EE && j == (n >> 3))
        g_cwdiag[b * EE + n] = cw[n & 7] * rs * rows;
}

// ---------------- K7: metric scalars ----------------
__global__ __launch_bounds__(256) void k_scalars(float* __restrict__ out) {
    __shared__ float red[256];
    int t = threadIdx.x;
    float v;

    v = 0.f; for (int i = t; i < BB * NN; i += 256) v += g_cwterm[i];
    red[t] = v; __syncthreads();
    for (int s = 128; s > 0; s >>= 1) { if (t < s) red[t] += red[t + s]; __syncthreads(); }
    float sumA = red[0]; __syncthreads();

    v = 0.f; for (int i = t; i < BB * EE; i += 256) v += g_cwdiag[i];
    red[t] = v; __syncthreads();
    for (int s = 128; s > 0; s >>= 1) { if (t < s) red[t] += red[t + s]; __syncthreads(); }
    float sumAd = red[0]; __syncthreads();

    v = 0.f; for (int i = t; i < BB * EE; i += 256) v += g_dwterm[i];
    red[t] = v; __syncthreads();
    for (int s = 128; s > 0; s >>= 1) { if (t < s) red[t] += red[t + s]; __syncthreads(); }
    float sumB = red[0]; __syncthreads();

    v = (t < BB) ? g_dwterm[t * EE] : 0.f;
    red[t] = v; __syncthreads();
    for (int s = 128; s > 0; s >>= 1) { if (t < s) red[t] += red[t + s]; __syncthreads(); }
    float sumB0 = red[0];

    if (t == 0) {
        out[(size_t)BB * NN * DD]     = (sumA - sumAd) / (float)(BB * (size_t)NN * (NN - 1));
        out[(size_t)BB * NN * DD + 1] = (sumB - sumB0) / (float)(BB * EE * (EE - 1));
    }
}

// ---------------- K8: w2 pass (h-split 32, gelu fused in staging) ----------------
// grid (x = dc(2) x hs(32) = 64, e=32) = 2048 blocks, 128 threads
__global__ __launch_bounds__(128) void k_w2(
    const float* __restrict__ w2, const float* __restrict__ b1) {
    int e = blockIdx.y;
    int dc = blockIdx.x & 1;
    int hs = blockIdx.x >> 1;
    int d0 = dc * 512 + threadIdx.x * 4;
    int h0 = hs * 128;

    __shared__ float4 hsm4[128];  // [hh] -> (b0,b1,b2,b3)
    for (int i = threadIdx.x; i < 4 * 128; i += 128) {
        int b = i >> 7, hh = i & 127;
        size_t hidx = (size_t)(e * 4 + b) * HH + h0 + hh;
        float v = b1[e * HH + h0 + hh];
#pragma unroll
        for (int p = 0; p < 8; p++) v += g_h1p[p][hidx];
        v = v * normcdff(v);
        reinterpret_cast<float*>(hsm4)[hh * 4 + b] = v;
    }
    __syncthreads();

    float4 a0 = make_float4(0.f, 0.f, 0.f, 0.f), a1 = a0, a2 = a0, a3 = a0;
    const float4* wp = reinterpret_cast<const float4*>(
        w2 + (size_t)e * HH * DD + (size_t)h0 * DD) + (d0 >> 2);
#pragma unroll 8
    for (int hh = 0; hh < 128; hh++) {
        float4 wv = __ldcs(wp);
        wp += (DD / 4);
        float4 hv = hsm4[hh];
        a0.x += hv.x * wv.x; a0.y += hv.x * wv.y; a0.z += hv.x * wv.z; a0.w += hv.x * wv.w;
        a1.x += hv.y * wv.x; a1.y += hv.y * wv.y; a1.z += hv.y * wv.z; a1.w += hv.y * wv.w;
        a2.x += hv.z * wv.x; a2.y += hv.z * wv.y; a2.z += hv.z * wv.z; a2.w += hv.z * wv.w;
        a3.x += hv.w * wv.x; a3.y += hv.w * wv.y; a3.z += hv.w * wv.z; a3.w += hv.w * wv.w;
    }
    *reinterpret_cast<float4*>(&g_eo_part[hs][((0 * EE) + e) * DD + d0]) = a0;
    *reinterpret_cast<float4*>(&g_eo_part[hs][((1 * EE) + e) * DD + d0]) = a1;
    *reinterpret_cast<float4*>(&g_eo_part[hs][((2 * EE) + e) * DD + d0]) = a2;
    *reinterpret_cast<float4*>(&g_eo_part[hs][((3 * EE) + e) * DD + d0]) = a3;
}

// ---------------- K9: reduce eo partials (+b2), vectorized ----------------
__global__ __launch_bounds__(256) void k_red_eo(const float* __restrict__ b2) {
    int i = blockIdx.x * 256 + threadIdx.x;  // 32768 float4s
    int e = (i >> 8) & (EE - 1);
    int dqd = i & 255;
    float4 s = reinterpret_cast<const float4*>(b2)[e * 256 + dqd];
#pragma unroll
    for (int p = 0; p < 32; p++) {
        float4 u = reinterpret_cast<const float4*>(g_eo_part[p])[i];
        s.x += u.x; s.y += u.y; s.z += u.z; s.w += u.w;
    }
    reinterpret_cast<float4*>(g_eo)[i] = s;
}

// ---------------- K10: out (register micro-tile GEMM over e) ----------------
// grid (dt=8, nt=32, b=4) = 1024 blocks; thread: 4n x 4d (float4)
__global__ __launch_bounds__(256) void k_out(float* __restrict__ out) {
    int dt = blockIdx.x;
    int nt = blockIdx.y;
    int b = blockIdx.z;
    int t = threadIdx.x;
    int td = t & 31;
    int tn = t >> 5;   // 0..7 -> rows tn*4..tn*4+3
    int d0 = dt * 128;
    int n0 = nt * 32;

    __shared__ float4 eos4[32][32];  // [e][d-quad], 16 KB
    __shared__ float cwTs[32][33];   // [e][nn]

    for (int i = t; i < 1024; i += 256) {
        int e = i >> 5, q = i & 31;
        eos4[e][q] = *reinterpret_cast<const float4*>(
            &g_eo[((b * EE) + e) * DD + d0 + q * 4]);
    }
    {
        int nn = t >> 3, equad = t & 7;   // 256 threads = 32 nn x 8 e-quads
        float4 v = *reinterpret_cast<const float4*>(
            &g_cw[((b * NN) + n0 + nn) * EE + equad * 4]);
        cwTs[equad * 4 + 0][nn] = v.x;
        cwTs[equad * 4 + 1][nn] = v.y;
        cwTs[equad * 4 + 2][nn] = v.z;
        cwTs[equad * 4 + 3][nn] = v.w;
    }
    __syncthreads();

    float4 a0 = make_float4(0.f, 0.f, 0.f, 0.f), a1 = a0, a2 = a0, a3 = a0;
#pragma unroll
    for (int e = 0; e < 32; e++) {
        float4 ev = eos4[e][td];
        float c0 = cwTs[e][tn * 4 + 0];
        float c1 = cwTs[e][tn * 4 + 1];
        float c2 = cwTs[e][tn * 4 + 2];
        float c3 = cwTs[e][tn * 4 + 3];
        a0.x += c0 * ev.x; a0.y += c0 * ev.y; a0.z += c0 * ev.z; a0.w += c0 * ev.w;
        a1.x += c1 * ev.x; a1.y += c1 * ev.y; a1.z += c1 * ev.z; a1.w += c1 * ev.w;
        a2.x += c2 * ev.x; a2.y += c2 * ev.y; a2.z += c2 * ev.z; a2.w += c2 * ev.w;
        a3.x += c3 * ev.x; a3.y += c3 * ev.y; a3.z += c3 * ev.z; a3.w += c3 * ev.w;
    }
    size_t base = ((size_t)(b * NN) + n0 + tn * 4) * DD + d0 + td * 4;
    *reinterpret_cast<float4*>(&out[base + 0 * DD]) = a0;
    *reinterpret_cast<float4*>(&out[base + 1 * DD]) = a1;
    *reinterpret_cast<float4*>(&out[base + 2 * DD]) = a2;
    *reinterpret_cast<float4*>(&out[base + 3 * DD]) = a3;
}

// ---------------- launch ----------------
extern "C" void kernel_launch(void* const* d_in, const int* in_sizes, int n_in,
                              void* d_out, int out_size) {
    const float* x   = (const float*)d_in[0];
    const float* phi = (const float*)d_in[1];
    const float* kg  = (const float*)d_in[2];
    const float* kb  = (const float*)d_in[3];
    const float* qg  = (const float*)d_in[4];
    const float* qb  = (const float*)d_in[5];
    const float* lg  = (const float*)d_in[6];
    const float* lb  = (const float*)d_in[7];
    const float* sc  = (const float*)d_in[8];
    const float* w1  = (const float*)d_in[9];
    const float* b1  = (const float*)d_in[10];
    const float* w2  = (const float*)d_in[11];
    const float* b2  = (const float*)d_in[12];
    float* out = (float*)d_out;

    k_qnorm<<<EE, 256>>>(phi, qg, qb, lg, lb, sc);
    k_logits<<<dim3(32, 4), 256>>>(x, kg, kb);
    k_dstats<<<BB * EE, 256>>>();
    k_slots<<<dim3(8, 16, 4), 256>>>(x);      // position 4 -> ncu capture (unchanged config)
    k_red_slots<<<128, 256>>>();
    k_w1<<<dim3(8, 8, 32), 128>>>(w1);
    k_combine<<<64, 256>>>();
    k_scalars<<<1, 256>>>(out);
    k_w2<<<dim3(64, 32), 128>>>(w2, b1);
    k_red_eo<<<128, 256>>>(b2);
    k_out<<<dim3(8, 32, 4), 256>>>(out);
}